// round 8
// baseline (speedup 1.0000x reference)
#include <cuda_runtime.h>
#include <cstdint>

#define NUM_U 200000
#define NUM_I 100000
#define NUM_E 500000
#define DIM_D 128
#define DIM_H 256
#define DIM_O 128

// ---------------- scratch (device globals; no allocation allowed) ----------
__device__ __align__(16) float g_agg1_u[(size_t)NUM_U * 128];  // zero-invariant
__device__ __align__(16) float g_agg1_i[(size_t)NUM_I * 128];  // zero-invariant
__device__ __align__(16) float g_agg2_u[(size_t)NUM_U * 256];  // zero-invariant
__device__ __align__(16) float g_agg2_i[(size_t)NUM_I * 256];  // zero-invariant
__device__ __align__(16) float g_h_u[(size_t)NUM_U * 256];
__device__ __align__(16) float g_h_i[(size_t)NUM_I * 256];
__device__ float g_dg_u[NUM_U];
__device__ float g_dg_i[NUM_I];
// transposed tf32 hi/lo weights: 8 matrices x 32768 elems, [N][K] layout, f32 storage
__device__ __align__(16) float g_wT_h[8 * 32768];
__device__ __align__(16) float g_wT_l[8 * 32768];

// ---------------- zero ------------------------------------------------------
__global__ void zero_kernel(float4* __restrict__ p, int n4) {
    int i = blockIdx.x * blockDim.x + threadIdx.x;
    if (i < n4) p[i] = make_float4(0.f, 0.f, 0.f, 0.f);
}

// ---------------- degrees ---------------------------------------------------
__global__ void deg_kernel(const int* __restrict__ src, const int* __restrict__ dst,
                           float* __restrict__ dg_u, float* __restrict__ dg_i) {
    int e = blockIdx.x * blockDim.x + threadIdx.x;
    if (e < NUM_E) {
        atomicAdd(dg_u + src[e], 1.f);
        atomicAdd(dg_i + dst[e], 1.f);
    }
}
__global__ void invdeg_kernel(float* __restrict__ dg, int n) {
    int i = blockIdx.x * blockDim.x + threadIdx.x;
    if (i < n) dg[i] = 1.f / fmaxf(dg[i], 1.f);
}

// ---------------- scatter-add (segment sum) --------------------------------
__global__ void scatter_kernel(const float* __restrict__ feat,
                               const int* __restrict__ gidx,
                               const int* __restrict__ sidx,
                               float* __restrict__ agg, int d4) {
    unsigned t = blockIdx.x * blockDim.x + threadIdx.x;
    unsigned e = t / d4;
    unsigned c = t % d4;
    if (e >= NUM_E) return;
    int g = gidx[e];
    int s = sidx[e];
    float4 v = reinterpret_cast<const float4*>(feat)[(size_t)g * d4 + c];
    float4* p = reinterpret_cast<float4*>(agg) + (size_t)s * d4 + c;
    asm volatile("red.global.add.v4.f32 [%0], {%1,%2,%3,%4};"
                 :: "l"(p), "f"(v.x), "f"(v.y), "f"(v.z), "f"(v.w) : "memory");
}

// ---------------- weight prep: transpose + tf32 hi/lo split -----------------
__global__ void prep_w(const float* __restrict__ W, float* __restrict__ oh,
                       float* __restrict__ ol, int K, int N) {
    int idx = blockIdx.x * blockDim.x + threadIdx.x;
    if (idx >= K * N) return;
    int k = idx / N, n = idx % N;
    float v = W[idx];
    uint32_t hb;
    asm("cvt.rna.tf32.f32 %0, %1;" : "=r"(hb) : "r"(__float_as_uint(v)));
    float hf = __uint_as_float(hb);
    float r = v - hf;
    uint32_t lb;
    asm("cvt.rna.tf32.f32 %0, %1;" : "=r"(lb) : "r"(__float_as_uint(r)));
    oh[n * K + k] = hf;
    ol[n * K + k] = __uint_as_float(lb);
}

// ---------------- mma helpers ------------------------------------------------
__device__ __forceinline__ uint32_t smem_u32(const void* p) {
    uint32_t a;
    asm("{ .reg .u64 t; cvta.to.shared.u64 t, %1; cvt.u32.u64 %0, t; }"
        : "=r"(a) : "l"(p));
    return a;
}
__device__ __forceinline__ uint32_t to_tf32(float v) {
    uint32_t t;
    asm("cvt.rna.tf32.f32 %0, %1;" : "=r"(t) : "r"(__float_as_uint(v)));
    return t;
}
__device__ __forceinline__ void mma_tf32(float* c, const uint32_t* a,
                                         const uint32_t* b) {
    asm volatile(
        "mma.sync.aligned.m16n8k8.row.col.f32.tf32.tf32.f32 "
        "{%0,%1,%2,%3}, {%4,%5,%6,%7}, {%8,%9}, {%0,%1,%2,%3};"
        : "+f"(c[0]), "+f"(c[1]), "+f"(c[2]), "+f"(c[3])
        : "r"(a[0]), "r"(a[1]), "r"(a[2]), "r"(a[3]), "r"(b[0]), "r"(b[1]));
}
__device__ __forceinline__ void cp16(uint32_t dst, const void* src, int sz) {
    asm volatile("cp.async.cg.shared.global [%0], [%1], 16, %2;"
                 :: "r"(dst), "l"(src), "r"(sz) : "memory");
}

// ---------------- fused SAGE GEMM: tf32 HMMA, fp32 activations --------------
// C = relu( invdeg[m]*(A0[m,:] @ Wl) + bias + A1[m,:] @ Wr )
// A fp32 -> tf32 in-register (1 term); W pre-split tf32 hi/lo (2 terms).
// CTA tile 128x128, 8 warps of 64x32, BK=32, cp.async double buffer.
// If zeroA0 != null (requires gridDim.x==1), epilogue zeroes A0 tile rows.
#define SROW 36                       // floats per smem row (32 + 4 pad)
#define ATILE_F (128 * SROW)          // 4608 floats per operand tile
#define ATILE_B (ATILE_F * 4)         // 18432 bytes
#define STAGE_F (3 * ATILE_F)         // A, Bh, Bl
#define STAGE_B (3 * ATILE_B)         // 55296
#define GEMM_SMEM (2 * STAGE_B)       // 110592
__global__ void __launch_bounds__(256)
sage_gemm_tf32(const float* __restrict__ A0, const float* __restrict__ inv,
               const float* __restrict__ A1,
               const float* __restrict__ Blh, const float* __restrict__ Bll,
               const float* __restrict__ Brh, const float* __restrict__ Brl,
               const float* __restrict__ bias, float* __restrict__ C,
               float* __restrict__ zeroA0,
               int M, int K, int N) {
    extern __shared__ __align__(16) float smem[];
    const uint32_t sbase = smem_u32(smem);

    const int tid = threadIdx.x;
    const int wid = tid >> 5, lane = tid & 31;
    const int wm = wid >> 2, wn = wid & 3;
    const int rowBase = blockIdx.y * 128, colBase = blockIdx.x * 128;
    const int cpp = K >> 5, nch = cpp * 2;

    const int ldR0 = tid >> 3, ldS = tid & 7;  // loader: row(step32), 16B seg
    const int qr = lane >> 2, qc = lane & 3;   // quad row/col within fragments

    float acc[4][4][4];
#pragma unroll
    for (int i = 0; i < 4; ++i)
#pragma unroll
        for (int j = 0; j < 4; ++j)
#pragma unroll
            for (int k = 0; k < 4; ++k) acc[i][j][k] = 0.f;

    auto issue = [&](int c) {
        const int phase = (c >= cpp);
        const int k0 = (c - (phase ? cpp : 0)) << 5;
        const float* A = phase ? A1 : A0;
        const float* Bh = phase ? Brh : Blh;
        const float* Bl = phase ? Brl : Bll;
        const uint32_t st = sbase + (c & 1) * STAGE_B;
#pragma unroll
        for (int it = 0; it < 4; ++it) {
            const int r = ldR0 + it * 32;
            const uint32_t doff = r * (SROW * 4) + ldS * 16;
            const int grow = rowBase + r;
            const int sz = (grow < M) ? 16 : 0;
            cp16(st + doff, A + (size_t)(grow < M ? grow : 0) * K + k0 + ldS * 4, sz);
            const size_t bo = (size_t)(colBase + r) * K + k0 + ldS * 4;
            cp16(st + ATILE_B + doff, Bh + bo, 16);
            cp16(st + 2 * ATILE_B + doff, Bl + bo, 16);
        }
        asm volatile("cp.async.commit_group;" ::: "memory");
    };

    issue(0);
    issue(1);

    for (int c = 0; c < nch; ++c) {
        if (c + 1 < nch)
            asm volatile("cp.async.wait_group 1;" ::: "memory");
        else
            asm volatile("cp.async.wait_group 0;" ::: "memory");
        __syncthreads();

        const float* sp = smem + (c & 1) * STAGE_F;
        const float* spBh = sp + ATILE_F;
        const float* spBl = sp + 2 * ATILE_F;

#pragma unroll
        for (int ks = 0; ks < 4; ++ks) {
            const int kk = ks * 8;
            uint32_t af[4][4];
#pragma unroll
            for (int fm = 0; fm < 4; ++fm) {
                const int base = (wm * 64 + fm * 16 + qr) * SROW + kk + qc;
                af[fm][0] = to_tf32(sp[base]);
                af[fm][1] = to_tf32(sp[base + 8 * SROW]);
                af[fm][2] = to_tf32(sp[base + 4]);
                af[fm][3] = to_tf32(sp[base + 8 * SROW + 4]);
            }
            uint32_t bh[4][2], bl[4][2];
#pragma unroll
            for (int fn = 0; fn < 4; ++fn) {
                const int base = (wn * 32 + fn * 8 + qr) * SROW + kk + qc;
                bh[fn][0] = __float_as_uint(spBh[base]);
                bh[fn][1] = __float_as_uint(spBh[base + 4]);
                bl[fn][0] = __float_as_uint(spBl[base]);
                bl[fn][1] = __float_as_uint(spBl[base + 4]);
            }
#pragma unroll
            for (int fm = 0; fm < 4; ++fm)
#pragma unroll
                for (int fn = 0; fn < 4; ++fn) {
                    mma_tf32(acc[fm][fn], af[fm], bh[fn]);
                    mma_tf32(acc[fm][fn], af[fm], bl[fn]);
                }
        }

        // phase boundary: acc holds A0@Wl partials only -> scale rows by invdeg
        if (c == cpp - 1) {
#pragma unroll
            for (int fm = 0; fm < 4; ++fm) {
                const int r0 = rowBase + wm * 64 + fm * 16 + qr;
                const int r1 = r0 + 8;
                const float s0 = (r0 < M) ? inv[r0] : 0.f;
                const float s1 = (r1 < M) ? inv[r1] : 0.f;
#pragma unroll
                for (int fn = 0; fn < 4; ++fn) {
                    acc[fm][fn][0] *= s0;
                    acc[fm][fn][1] *= s0;
                    acc[fm][fn][2] *= s1;
                    acc[fm][fn][3] *= s1;
                }
            }
        }

        __syncthreads();
        if (c + 2 < nch) issue(c + 2);
    }

    // ---- epilogue: bias + relu + store ----
#pragma unroll
    for (int fm = 0; fm < 4; ++fm) {
        const int r0 = rowBase + wm * 64 + fm * 16 + qr;
        const int r1 = r0 + 8;
#pragma unroll
        for (int fn = 0; fn < 4; ++fn) {
            const int col = colBase + wn * 32 + fn * 8 + qc * 2;
            const float b0 = bias[col], b1 = bias[col + 1];
            if (r0 < M) {
                float2 o;
                o.x = fmaxf(acc[fm][fn][0] + b0, 0.f);
                o.y = fmaxf(acc[fm][fn][1] + b1, 0.f);
                *(float2*)(C + (size_t)r0 * N + col) = o;
            }
            if (r1 < M) {
                float2 o;
                o.x = fmaxf(acc[fm][fn][2] + b0, 0.f);
                o.y = fmaxf(acc[fm][fn][3] + b1, 0.f);
                *(float2*)(C + (size_t)r1 * N + col) = o;
            }
        }
    }

    // ---- fused re-zero of A0 tile (sole reader when gridDim.x == 1) ----
    if (zeroA0) {
        const int k4 = K >> 2;
        for (int i = tid; i < 128 * k4; i += 256) {
            const int r = i / k4, cc = i % k4;
            if (rowBase + r < M)
                reinterpret_cast<float4*>(zeroA0 + (size_t)(rowBase + r) * K)[cc] =
                    make_float4(0.f, 0.f, 0.f, 0.f);
        }
    }
}

// ---------------- host launch ------------------------------------------------
static inline int cdiv(int a, int b) { return (a + b - 1) / b; }

extern "C" void kernel_launch(void* const* d_in, const int* in_sizes, int n_in,
                              void* d_out, int out_size) {
    const float* x_user = (const float*)d_in[0];
    const float* x_item = (const float*)d_in[1];
    const int* e_src = (const int*)d_in[2];
    const int* e_dst = (const int*)d_in[3];
    const float* Wl1_ui = (const float*)d_in[4];
    const float* Wr1_ui = (const float*)d_in[5];
    const float* bl1_ui = (const float*)d_in[6];
    const float* Wl1_iu = (const float*)d_in[7];
    const float* Wr1_iu = (const float*)d_in[8];
    const float* bl1_iu = (const float*)d_in[9];
    const float* Wl2_ui = (const float*)d_in[10];
    const float* Wr2_ui = (const float*)d_in[11];
    const float* bl2_ui = (const float*)d_in[12];
    const float* Wl2_iu = (const float*)d_in[13];
    const float* Wr2_iu = (const float*)d_in[14];
    const float* bl2_iu = (const float*)d_in[15];
    float* out = (float*)d_out;

    float *a1_u, *a1_i, *a2_u, *a2_i, *h_u, *h_i, *dg_u, *dg_i, *wTh, *wTl;
    cudaGetSymbolAddress((void**)&a1_u, g_agg1_u);
    cudaGetSymbolAddress((void**)&a1_i, g_agg1_i);
    cudaGetSymbolAddress((void**)&a2_u, g_agg2_u);
    cudaGetSymbolAddress((void**)&a2_i, g_agg2_i);
    cudaGetSymbolAddress((void**)&h_u, g_h_u);
    cudaGetSymbolAddress((void**)&h_i, g_h_i);
    cudaGetSymbolAddress((void**)&dg_u, g_dg_u);
    cudaGetSymbolAddress((void**)&dg_i, g_dg_i);
    cudaGetSymbolAddress((void**)&wTh, g_wT_h);
    cudaGetSymbolAddress((void**)&wTl, g_wT_l);

    cudaFuncSetAttribute(sage_gemm_tf32, cudaFuncAttributeMaxDynamicSharedMemorySize,
                         GEMM_SMEM);

    const int TB = 256;

    // --- degrees (5 launches; ncu -s 5 captures the next launch = L1 scatter) ---
    zero_kernel<<<cdiv(NUM_U / 4, TB), TB>>>((float4*)dg_u, NUM_U / 4);
    zero_kernel<<<cdiv(NUM_I / 4, TB), TB>>>((float4*)dg_i, NUM_I / 4);
    deg_kernel<<<cdiv(NUM_E, TB), TB>>>(e_src, e_dst, dg_u, dg_i);
    invdeg_kernel<<<cdiv(NUM_U, TB), TB>>>(dg_u, NUM_U);
    invdeg_kernel<<<cdiv(NUM_I, TB), TB>>>(dg_i, NUM_I);

    // --- layer-1 scatter (agg1 zero by invariant; D=128 -> d4=32) ---
    {
        int nb = cdiv(NUM_E * 32, TB);
        scatter_kernel<<<nb, TB>>>(x_user, e_src, e_dst, a1_i, 32);
        scatter_kernel<<<nb, TB>>>(x_item, e_dst, e_src, a1_u, 32);
    }

    // --- weight prep: transpose + tf32 hi/lo split ---
    {
        const float* Ws[8] = {Wl1_ui, Wr1_ui, Wl1_iu, Wr1_iu,
                              Wl2_ui, Wr2_ui, Wl2_iu, Wr2_iu};
        const int Ks[8] = {128, 128, 128, 128, 256, 256, 256, 256};
        const int Ns[8] = {256, 256, 256, 256, 128, 128, 128, 128};
        for (int m = 0; m < 8; ++m)
            prep_w<<<cdiv(32768, TB), TB>>>(Ws[m], wTh + m * 32768, wTl + m * 32768,
                                            Ks[m], Ns[m]);
    }

    // --- layer-1 GEMMs: [M,128]@[128,256] -> h (fp32) ---
    {
        dim3 gi(2, cdiv(NUM_I, 128));
        sage_gemm_tf32<<<gi, 256, GEMM_SMEM>>>(a1_i, dg_i, x_item,
            wTh + 0 * 32768, wTl + 0 * 32768, wTh + 1 * 32768, wTl + 1 * 32768,
            bl1_ui, h_i, nullptr, NUM_I, DIM_D, DIM_H);
        dim3 gu(2, cdiv(NUM_U, 128));
        sage_gemm_tf32<<<gu, 256, GEMM_SMEM>>>(a1_u, dg_u, x_user,
            wTh + 2 * 32768, wTl + 2 * 32768, wTh + 3 * 32768, wTl + 3 * 32768,
            bl1_iu, h_u, nullptr, NUM_U, DIM_D, DIM_H);
    }

    // --- restore agg1 zero invariant (grid.x=2 above forbids fused zeroing) ---
    zero_kernel<<<cdiv(NUM_U * 32, TB), TB>>>((float4*)a1_u, NUM_U * 32);
    zero_kernel<<<cdiv(NUM_I * 32, TB), TB>>>((float4*)a1_i, NUM_I * 32);

    // --- layer-2 scatter (agg2 zero by L2-GEMM-epilogue invariant; d4=64) ---
    {
        int nb = cdiv(NUM_E * 64, TB);
        scatter_kernel<<<nb, TB>>>(h_u, e_src, e_dst, a2_i, 64);
        scatter_kernel<<<nb, TB>>>(h_i, e_dst, e_src, a2_u, 64);
    }

    // --- layer-2 GEMMs: [M,256]@[256,128] -> out; epilogue re-zeroes agg2 ---
    {
        dim3 gi(1, cdiv(NUM_I, 128));
        sage_gemm_tf32<<<gi, 256, GEMM_SMEM>>>(a2_i, dg_i, h_i,
            wTh + 4 * 32768, wTl + 4 * 32768, wTh + 5 * 32768, wTl + 5 * 32768,
            bl2_ui, out + (size_t)NUM_U * DIM_O, a2_i, NUM_I, DIM_H, DIM_O);
        dim3 gu(1, cdiv(NUM_U, 128));
        sage_gemm_tf32<<<gu, 256, GEMM_SMEM>>>(a2_u, dg_u, h_u,
            wTh + 6 * 32768, wTl + 6 * 32768, wTh + 7 * 32768, wTl + 7 * 32768,
            bl2_iu, out, a2_u, NUM_U, DIM_H, DIM_O);
    }
}

// round 9
// speedup vs baseline: 1.1552x; 1.1552x over previous
#include <cuda_runtime.h>
#include <cuda_bf16.h>
#include <cstdint>

#define NUM_U 200000
#define NUM_I 100000
#define NUM_E 500000
#define DIM_D 128
#define DIM_H 256
#define DIM_O 128

// ---------------- scratch (device globals; no allocation allowed) ----------
__device__ __align__(16) float g_agg1_u[(size_t)NUM_U * 128];  // zero-invariant
__device__ __align__(16) float g_agg1_i[(size_t)NUM_I * 128];  // zero-invariant
__device__ __align__(16) float g_agg2_u[(size_t)NUM_U * 128];  // zero-invariant
__device__ __align__(16) float g_agg2_i[(size_t)NUM_I * 128];  // zero-invariant
__device__ __align__(16) float g_p_u[(size_t)NUM_U * 128];     // h_u @ Wl2_ui
__device__ __align__(16) float g_p_i[(size_t)NUM_I * 128];     // h_i @ Wl2_iu
__device__ float g_dg_u[NUM_U];
__device__ float g_dg_i[NUM_I];
// bf16 hi/lo splits
__device__ __align__(16) uint16_t g_xh_u[(size_t)NUM_U * 128];
__device__ __align__(16) uint16_t g_xl_u[(size_t)NUM_U * 128];
__device__ __align__(16) uint16_t g_xh_i[(size_t)NUM_I * 128];
__device__ __align__(16) uint16_t g_xl_i[(size_t)NUM_I * 128];
__device__ __align__(16) uint16_t g_a1h_u[(size_t)NUM_U * 128];
__device__ __align__(16) uint16_t g_a1l_u[(size_t)NUM_U * 128];
__device__ __align__(16) uint16_t g_a1h_i[(size_t)NUM_I * 128];
__device__ __align__(16) uint16_t g_a1l_i[(size_t)NUM_I * 128];
__device__ __align__(16) uint16_t g_hh_u[(size_t)NUM_U * 256];
__device__ __align__(16) uint16_t g_hl_u[(size_t)NUM_U * 256];
__device__ __align__(16) uint16_t g_hh_i[(size_t)NUM_I * 256];
__device__ __align__(16) uint16_t g_hl_i[(size_t)NUM_I * 256];
// transposed bf16 hi/lo weights: 8 matrices x 32768 elems, [N][K] layout
__device__ __align__(16) uint16_t g_wT_h[8 * 32768];
__device__ __align__(16) uint16_t g_wT_l[8 * 32768];

// ---------------- zero ------------------------------------------------------
__global__ void zero_kernel(float4* __restrict__ p, int n4) {
    int i = blockIdx.x * blockDim.x + threadIdx.x;
    if (i < n4) p[i] = make_float4(0.f, 0.f, 0.f, 0.f);
}

// ---------------- degrees ---------------------------------------------------
__global__ void deg_kernel(const int* __restrict__ src, const int* __restrict__ dst,
                           float* __restrict__ dg_u, float* __restrict__ dg_i) {
    int e = blockIdx.x * blockDim.x + threadIdx.x;
    if (e < NUM_E) {
        atomicAdd(dg_u + src[e], 1.f);
        atomicAdd(dg_i + dst[e], 1.f);
    }
}
__global__ void invdeg_kernel(float* __restrict__ dg, int n) {
    int i = blockIdx.x * blockDim.x + threadIdx.x;
    if (i < n) dg[i] = 1.f / fmaxf(dg[i], 1.f);
}

// ---------------- scatter-add (segment sum), 128-wide rows ------------------
__global__ void scatter_kernel(const float* __restrict__ feat,
                               const int* __restrict__ gidx,
                               const int* __restrict__ sidx,
                               float* __restrict__ agg, int d4) {
    unsigned t = blockIdx.x * blockDim.x + threadIdx.x;
    unsigned e = t / d4;
    unsigned c = t % d4;
    if (e >= NUM_E) return;
    int g = gidx[e];
    int s = sidx[e];
    float4 v = reinterpret_cast<const float4*>(feat)[(size_t)g * d4 + c];
    float4* p = reinterpret_cast<float4*>(agg) + (size_t)s * d4 + c;
    asm volatile("red.global.add.v4.f32 [%0], {%1,%2,%3,%4};"
                 :: "l"(p), "f"(v.x), "f"(v.y), "f"(v.z), "f"(v.w) : "memory");
}

// ---------------- weight prep: transpose + bf16 hi/lo split -----------------
__global__ void prep_w(const float* __restrict__ W, uint16_t* __restrict__ oh,
                       uint16_t* __restrict__ ol, int K, int N) {
    int idx = blockIdx.x * blockDim.x + threadIdx.x;
    if (idx >= K * N) return;
    int k = idx / N, n = idx % N;
    float v = W[idx];
    __nv_bfloat16 h = __float2bfloat16_rn(v);
    float r = v - __bfloat162float(h);
    __nv_bfloat16 l = __float2bfloat16_rn(r);
    oh[n * K + k] = *reinterpret_cast<uint16_t*>(&h);
    ol[n * K + k] = *reinterpret_cast<uint16_t*>(&l);
}

// ---------------- bf16 hi/lo split pass (opt: scale by invdeg, zero src) ----
__global__ void split_kernel(const float4* in, float4* zro,
                             const float* __restrict__ inv,
                             uint2* __restrict__ ah, uint2* __restrict__ al,
                             int n4, int k4) {
    int i = blockIdx.x * blockDim.x + threadIdx.x;
    if (i >= n4) return;
    float4 v = in[i];
    if (inv) {
        float sc = inv[i / k4];
        v.x *= sc; v.y *= sc; v.z *= sc; v.w *= sc;
    }
    uint32_t h01, h23;
    asm("cvt.rn.bf16x2.f32 %0, %1, %2;" : "=r"(h01) : "f"(v.y), "f"(v.x));
    asm("cvt.rn.bf16x2.f32 %0, %1, %2;" : "=r"(h23) : "f"(v.w), "f"(v.z));
    float r0 = v.x - __uint_as_float(h01 << 16);
    float r1 = v.y - __uint_as_float(h01 & 0xFFFF0000u);
    float r2 = v.z - __uint_as_float(h23 << 16);
    float r3 = v.w - __uint_as_float(h23 & 0xFFFF0000u);
    uint32_t l01, l23;
    asm("cvt.rn.bf16x2.f32 %0, %1, %2;" : "=r"(l01) : "f"(r1), "f"(r0));
    asm("cvt.rn.bf16x2.f32 %0, %1, %2;" : "=r"(l23) : "f"(r3), "f"(r2));
    ah[i] = make_uint2(h01, h23);
    al[i] = make_uint2(l01, l23);
    if (zro) zro[i] = make_float4(0.f, 0.f, 0.f, 0.f);
}

// ---------------- mma.sync helpers ------------------------------------------
__device__ __forceinline__ uint32_t smem_u32(const void* p) {
    uint32_t a;
    asm("{ .reg .u64 t; cvta.to.shared.u64 t, %1; cvt.u32.u64 %0, t; }"
        : "=r"(a) : "l"(p));
    return a;
}
__device__ __forceinline__ void ldm_x4(uint32_t addr, uint32_t& r0, uint32_t& r1,
                                       uint32_t& r2, uint32_t& r3) {
    asm volatile("ldmatrix.sync.aligned.m8n8.x4.shared.b16 {%0,%1,%2,%3}, [%4];"
                 : "=r"(r0), "=r"(r1), "=r"(r2), "=r"(r3) : "r"(addr));
}
__device__ __forceinline__ void mma_bf16(float* c, const uint32_t* a,
                                         const uint32_t* b) {
    asm volatile(
        "mma.sync.aligned.m16n8k16.row.col.f32.bf16.bf16.f32 "
        "{%0,%1,%2,%3}, {%4,%5,%6,%7}, {%8,%9}, {%0,%1,%2,%3};"
        : "+f"(c[0]), "+f"(c[1]), "+f"(c[2]), "+f"(c[3])
        : "r"(a[0]), "r"(a[1]), "r"(a[2]), "r"(a[3]), "r"(b[0]), "r"(b[1]));
}
__device__ __forceinline__ void cp16(uint32_t dst, const void* src, int sz) {
    asm volatile("cp.async.cg.shared.global [%0], [%1], 16, %2;"
                 :: "r"(dst), "l"(src), "r"(sz) : "memory");
}

// ---------------- fused SAGE GEMM on HMMA, pre-split bf16, 2-stage pipe -----
// Two-phase (Ah0 != null):  C = eps( A0@Wl + A1@Wr )   [Wl=Bl*, Wr=Br*]
// Single-phase (Ah0 == null): C = eps( A1@Wl )
// eps(v): if Eagg: v += inv[m]*Eagg[m,n]; if bias: v = relu(v + bias[n]).
// Optional: emit bf16 hi/lo split of result (Hh/Hl); zero Eagg tile (zeroE,
// requires gridDim.x == 1).
#define SROW 72                      // bf16 elems per smem row (64 + 8 pad)
#define TILE_B (128 * SROW * 2)      // 18432 bytes per operand tile
#define STAGE_B (4 * TILE_B)         // Ah, Al, Bh, Bl
#define GEMM_SMEM (2 * STAGE_B)      // 147456
__global__ void __launch_bounds__(256)
sage_gemm_bf16(const uint16_t* __restrict__ Ah0, const uint16_t* __restrict__ Al0,
               const uint16_t* __restrict__ Ah1, const uint16_t* __restrict__ Al1,
               const uint16_t* __restrict__ Blh, const uint16_t* __restrict__ Bll,
               const uint16_t* __restrict__ Brh, const uint16_t* __restrict__ Brl,
               const float* __restrict__ bias, float* __restrict__ C,
               uint16_t* __restrict__ Hh, uint16_t* __restrict__ Hl,
               const float* __restrict__ Eagg, const float* __restrict__ inv,
               float* __restrict__ zeroE,
               int M, int K, int N) {
    extern __shared__ __align__(16) uint16_t smem[];
    const uint32_t sbase = smem_u32(smem);

    const int tid = threadIdx.x;
    const int wid = tid >> 5, lane = tid & 31;
    const int wm = wid >> 2, wn = wid & 3;
    const int rowBase = blockIdx.y * 128, colBase = blockIdx.x * 128;
    const int cpp = K >> 6;
    const bool twoPhase = (Ah0 != nullptr);
    const int nch = (twoPhase ? 2 : 1) * cpp;
    const uint16_t* ah0 = twoPhase ? Ah0 : Ah1;
    const uint16_t* al0 = twoPhase ? Al0 : Al1;

    const int ldR0 = tid >> 3, ldS = tid & 7;

    const int aRow = lane & 15, aColH = (lane >> 4) * 8;
    const int bRow = ((lane >> 4) & 1) * 8 + (lane & 7);
    const int bColH = ((lane >> 3) & 1) * 8;

    float acc[4][4][4];
#pragma unroll
    for (int i = 0; i < 4; ++i)
#pragma unroll
        for (int j = 0; j < 4; ++j)
#pragma unroll
            for (int k = 0; k < 4; ++k) acc[i][j][k] = 0.f;

    auto issue = [&](int c) {
        const int phase = (c >= cpp) ? 1 : 0;
        const int k0 = (c - (phase ? cpp : 0)) * 64;
        const uint16_t* ah = phase ? Ah1 : ah0;
        const uint16_t* al = phase ? Al1 : al0;
        const uint16_t* bh = phase ? Brh : Blh;
        const uint16_t* bl = phase ? Brl : Bll;
        const uint32_t st = sbase + (c & 1) * STAGE_B;
#pragma unroll
        for (int it = 0; it < 4; ++it) {
            const int r = ldR0 + it * 32;
            const uint32_t doff = r * (SROW * 2) + ldS * 16;
            const int grow = rowBase + r;
            const int sz = (grow < M) ? 16 : 0;
            const size_t aoff = (size_t)(grow < M ? grow : 0) * K + k0 + ldS * 8;
            cp16(st + doff, ah + aoff, sz);
            cp16(st + TILE_B + doff, al + aoff, sz);
            const size_t boff = (size_t)(colBase + r) * K + k0 + ldS * 8;
            cp16(st + 2 * TILE_B + doff, bh + boff, 16);
            cp16(st + 3 * TILE_B + doff, bl + boff, 16);
        }
        asm volatile("cp.async.commit_group;" ::: "memory");
    };

    issue(0);
    if (nch > 1) issue(1);

    for (int c = 0; c < nch; ++c) {
        if (c + 1 < nch)
            asm volatile("cp.async.wait_group 1;" ::: "memory");
        else
            asm volatile("cp.async.wait_group 0;" ::: "memory");
        __syncthreads();

        const uint32_t st = sbase + (c & 1) * STAGE_B;
#pragma unroll
        for (int ks = 0; ks < 4; ++ks) {
            const int kk = ks * 16;
            uint32_t ah[4][4], al[4][4];
#pragma unroll
            for (int fm = 0; fm < 4; ++fm) {
                uint32_t off = st + 2u * ((wm * 64 + fm * 16 + aRow) * SROW + kk + aColH);
                ldm_x4(off, ah[fm][0], ah[fm][1], ah[fm][2], ah[fm][3]);
                ldm_x4(off + TILE_B, al[fm][0], al[fm][1], al[fm][2], al[fm][3]);
            }
            uint32_t bh[4][2], bl[4][2];
#pragma unroll
            for (int g = 0; g < 2; ++g) {
                uint32_t off = st + 2 * TILE_B +
                               2u * ((wn * 32 + g * 16 + bRow) * SROW + kk + bColH);
                ldm_x4(off, bh[2 * g][0], bh[2 * g][1], bh[2 * g + 1][0], bh[2 * g + 1][1]);
                ldm_x4(off + TILE_B, bl[2 * g][0], bl[2 * g][1],
                       bl[2 * g + 1][0], bl[2 * g + 1][1]);
            }
#pragma unroll
            for (int fm = 0; fm < 4; ++fm)
#pragma unroll
                for (int fn = 0; fn < 4; ++fn) {
                    mma_bf16(acc[fm][fn], ah[fm], bh[fn]);
                    mma_bf16(acc[fm][fn], al[fm], bh[fn]);
                    mma_bf16(acc[fm][fn], ah[fm], bl[fn]);
                }
        }
        __syncthreads();
        if (c + 2 < nch) issue(c + 2);
    }

    // ---- epilogue ----
#pragma unroll
    for (int fm = 0; fm < 4; ++fm) {
        const int r0 = rowBase + wm * 64 + fm * 16 + (lane >> 2);
        const int r1 = r0 + 8;
#pragma unroll
        for (int fn = 0; fn < 4; ++fn) {
            const int col = colBase + wn * 32 + fn * 8 + (lane & 3) * 2;
#pragma unroll
            for (int half = 0; half < 2; ++half) {
                const int rr = half ? r1 : r0;
                if (rr >= M) continue;
                float vx = acc[fm][fn][half * 2 + 0];
                float vy = acc[fm][fn][half * 2 + 1];
                const size_t off = (size_t)rr * N + col;
                if (Eagg) {
                    float2 e = *(const float2*)(Eagg + off);
                    float s = inv[rr];
                    vx += s * e.x;
                    vy += s * e.y;
                }
                if (bias) {
                    vx = fmaxf(vx + bias[col], 0.f);
                    vy = fmaxf(vy + bias[col + 1], 0.f);
                }
                float2 o = make_float2(vx, vy);
                if (C) *(float2*)(C + off) = o;
                if (Hh) {
                    uint32_t ph;
                    asm("cvt.rn.bf16x2.f32 %0, %1, %2;" : "=r"(ph) : "f"(vy), "f"(vx));
                    float q0 = vx - __uint_as_float(ph << 16);
                    float q1 = vy - __uint_as_float(ph & 0xFFFF0000u);
                    uint32_t pl;
                    asm("cvt.rn.bf16x2.f32 %0, %1, %2;" : "=r"(pl) : "f"(q1), "f"(q0));
                    *(uint32_t*)(Hh + off) = ph;
                    *(uint32_t*)(Hl + off) = pl;
                }
            }
        }
    }

    // ---- fused re-zero of Eagg tile (sole reader when gridDim.x == 1) ----
    if (zeroE) {
        __syncthreads();
        const int n4 = N >> 2;
        for (int i = tid; i < 128 * n4; i += 256) {
            const int r = i / n4, cc = i % n4;
            if (rowBase + r < M)
                reinterpret_cast<float4*>(zeroE + (size_t)(rowBase + r) * N)[cc] =
                    make_float4(0.f, 0.f, 0.f, 0.f);
        }
    }
}

// ---------------- host launch ------------------------------------------------
static inline int cdiv(int a, int b) { return (a + b - 1) / b; }

extern "C" void kernel_launch(void* const* d_in, const int* in_sizes, int n_in,
                              void* d_out, int out_size) {
    const float* x_user = (const float*)d_in[0];
    const float* x_item = (const float*)d_in[1];
    const int* e_src = (const int*)d_in[2];
    const int* e_dst = (const int*)d_in[3];
    const float* Wl1_ui = (const float*)d_in[4];
    const float* Wr1_ui = (const float*)d_in[5];
    const float* bl1_ui = (const float*)d_in[6];
    const float* Wl1_iu = (const float*)d_in[7];
    const float* Wr1_iu = (const float*)d_in[8];
    const float* bl1_iu = (const float*)d_in[9];
    const float* Wl2_ui = (const float*)d_in[10];
    const float* Wr2_ui = (const float*)d_in[11];
    const float* bl2_ui = (const float*)d_in[12];
    const float* Wl2_iu = (const float*)d_in[13];
    const float* Wr2_iu = (const float*)d_in[14];
    const float* bl2_iu = (const float*)d_in[15];
    float* out = (float*)d_out;

    float *a1_u, *a1_i, *a2_u, *a2_i, *p_u, *p_i, *dg_u, *dg_i;
    uint16_t *xh_u, *xl_u, *xh_i, *xl_i, *a1h_u, *a1l_u, *a1h_i, *a1l_i;
    uint16_t *hh_u, *hl_u, *hh_i, *hl_i, *wTh, *wTl;
    cudaGetSymbolAddress((void**)&a1_u, g_agg1_u);
    cudaGetSymbolAddress((void**)&a1_i, g_agg1_i);
    cudaGetSymbolAddress((void**)&a2_u, g_agg2_u);
    cudaGetSymbolAddress((void**)&a2_i, g_agg2_i);
    cudaGetSymbolAddress((void**)&p_u, g_p_u);
    cudaGetSymbolAddress((void**)&p_i, g_p_i);
    cudaGetSymbolAddress((void**)&dg_u, g_dg_u);
    cudaGetSymbolAddress((void**)&dg_i, g_dg_i);
    cudaGetSymbolAddress((void**)&xh_u, g_xh_u);
    cudaGetSymbolAddress((void**)&xl_u, g_xl_u);
    cudaGetSymbolAddress((void**)&xh_i, g_xh_i);
    cudaGetSymbolAddress((void**)&xl_i, g_xl_i);
    cudaGetSymbolAddress((void**)&a1h_u, g_a1h_u);
    cudaGetSymbolAddress((void**)&a1l_u, g_a1l_u);
    cudaGetSymbolAddress((void**)&a1h_i, g_a1h_i);
    cudaGetSymbolAddress((void**)&a1l_i, g_a1l_i);
    cudaGetSymbolAddress((void**)&hh_u, g_hh_u);
    cudaGetSymbolAddress((void**)&hl_u, g_hl_u);
    cudaGetSymbolAddress((void**)&hh_i, g_hh_i);
    cudaGetSymbolAddress((void**)&hl_i, g_hl_i);
    cudaGetSymbolAddress((void**)&wTh, g_wT_h);
    cudaGetSymbolAddress((void**)&wTl, g_wT_l);

    cudaFuncSetAttribute(sage_gemm_bf16, cudaFuncAttributeMaxDynamicSharedMemorySize,
                         GEMM_SMEM);

    const int TB = 256;

    // --- launches 1-5: x splits, dg zero, deg ---
    split_kernel<<<cdiv(NUM_U * 32, TB), TB>>>((const float4*)x_user, nullptr, nullptr,
                                               (uint2*)xh_u, (uint2*)xl_u, NUM_U * 32, 32);
    split_kernel<<<cdiv(NUM_I * 32, TB), TB>>>((const float4*)x_item, nullptr, nullptr,
                                               (uint2*)xh_i, (uint2*)xl_i, NUM_I * 32, 32);
    zero_kernel<<<cdiv(NUM_U / 4, TB), TB>>>((float4*)dg_u, NUM_U / 4);
    zero_kernel<<<cdiv(NUM_I / 4, TB), TB>>>((float4*)dg_i, NUM_I / 4);
    deg_kernel<<<cdiv(NUM_E, TB), TB>>>(e_src, e_dst, dg_u, dg_i);

    // --- launch 6 (ncu -s 5 target): layer-1 scatter ---
    {
        int nb = cdiv(NUM_E * 32, TB);
        scatter_kernel<<<nb, TB>>>(x_user, e_src, e_dst, a1_i, 32);
        scatter_kernel<<<nb, TB>>>(x_item, e_dst, e_src, a1_u, 32);
    }

    invdeg_kernel<<<cdiv(NUM_U, TB), TB>>>(dg_u, NUM_U);
    invdeg_kernel<<<cdiv(NUM_I, TB), TB>>>(dg_i, NUM_I);

    // --- weight prep: transpose + bf16 hi/lo split ---
    {
        const float* Ws[8] = {Wl1_ui, Wr1_ui, Wl1_iu, Wr1_iu,
                              Wl2_ui, Wr2_ui, Wl2_iu, Wr2_iu};
        const int Ks[8] = {128, 128, 128, 128, 256, 256, 256, 256};
        const int Ns[8] = {256, 256, 256, 256, 128, 128, 128, 128};
        for (int m = 0; m < 8; ++m)
            prep_w<<<cdiv(32768, TB), TB>>>(Ws[m], wTh + m * 32768, wTl + m * 32768,
                                            Ks[m], Ns[m]);
    }

    // --- layer-1 agg split (scale by invdeg, re-zero agg1) ---
    split_kernel<<<cdiv(NUM_I * 32, TB), TB>>>((const float4*)a1_i, (float4*)a1_i,
                                               dg_i, (uint2*)a1h_i, (uint2*)a1l_i,
                                               NUM_I * 32, 32);
    split_kernel<<<cdiv(NUM_U * 32, TB), TB>>>((const float4*)a1_u, (float4*)a1_u,
                                               dg_u, (uint2*)a1h_u, (uint2*)a1l_u,
                                               NUM_U * 32, 32);

    // --- layer-1 GEMMs: two-phase [M,128]@[128,256]; emit h as bf16 split only ---
    {
        dim3 gi(2, cdiv(NUM_I, 128));
        sage_gemm_bf16<<<gi, 256, GEMM_SMEM>>>(a1h_i, a1l_i, xh_i, xl_i,
            wTh + 0 * 32768, wTl + 0 * 32768, wTh + 1 * 32768, wTl + 1 * 32768,
            bl1_ui, nullptr, hh_i, hl_i, nullptr, nullptr, nullptr,
            NUM_I, DIM_D, DIM_H);
        dim3 gu(2, cdiv(NUM_U, 128));
        sage_gemm_bf16<<<gu, 256, GEMM_SMEM>>>(a1h_u, a1l_u, xh_u, xl_u,
            wTh + 2 * 32768, wTl + 2 * 32768, wTh + 3 * 32768, wTl + 3 * 32768,
            bl1_iu, nullptr, hh_u, hl_u, nullptr, nullptr, nullptr,
            NUM_U, DIM_D, DIM_H);
    }

    // --- projection GEMMs (project-first): p = h @ Wl2, linear, fp32 out ---
    {
        dim3 gu(1, cdiv(NUM_U, 128));
        sage_gemm_bf16<<<gu, 256, GEMM_SMEM>>>(nullptr, nullptr, hh_u, hl_u,
            wTh + 4 * 32768, wTl + 4 * 32768, nullptr, nullptr,
            nullptr, p_u, nullptr, nullptr, nullptr, nullptr, nullptr,
            NUM_U, DIM_H, DIM_O);
        dim3 gi(1, cdiv(NUM_I, 128));
        sage_gemm_bf16<<<gi, 256, GEMM_SMEM>>>(nullptr, nullptr, hh_i, hl_i,
            wTh + 6 * 32768, wTl + 6 * 32768, nullptr, nullptr,
            nullptr, p_i, nullptr, nullptr, nullptr, nullptr, nullptr,
            NUM_I, DIM_H, DIM_O);
    }

    // --- layer-2 scatter: scatter projected p (128-wide) ---
    {
        int nb = cdiv(NUM_E * 32, TB);
        scatter_kernel<<<nb, TB>>>(p_u, e_src, e_dst, a2_i, 32);
        scatter_kernel<<<nb, TB>>>(p_i, e_dst, e_src, a2_u, 32);
    }

    // --- layer-2 GEMMs: single-phase h@Wr2 + epilogue inv*agg2 + bias + relu;
    //     epilogue re-zeroes agg2 (gridDim.x == 1) ---
    {
        dim3 gi(1, cdiv(NUM_I, 128));
        sage_gemm_bf16<<<gi, 256, GEMM_SMEM>>>(nullptr, nullptr, hh_i, hl_i,
            wTh + 5 * 32768, wTl + 5 * 32768, nullptr, nullptr,
            bl2_ui, out + (size_t)NUM_U * DIM_O, nullptr, nullptr,
            a2_i, dg_i, a2_i, NUM_I, DIM_H, DIM_O);
        dim3 gu(1, cdiv(NUM_U, 128));
        sage_gemm_bf16<<<gu, 256, GEMM_SMEM>>>(nullptr, nullptr, hh_u, hl_u,
            wTh + 7 * 32768, wTl + 7 * 32768, nullptr, nullptr,
            bl2_iu, out, nullptr, nullptr,
            a2_u, dg_u, a2_u, NUM_U, DIM_H, DIM_O);
    }
}

// round 10
// speedup vs baseline: 1.7039x; 1.4750x over previous
#include <cuda_runtime.h>
#include <cuda_fp16.h>
#include <cstdint>

#define NUM_U 200000
#define NUM_I 100000
#define NUM_E 500000
#define DIM_D 128
#define DIM_H 256
#define DIM_O 128

// ---------------- scratch (device globals; no allocation allowed) ----------
__device__ __align__(16) float g_agg1_u[(size_t)NUM_U * 128];  // zero-invariant
__device__ __align__(16) float g_agg1_i[(size_t)NUM_I * 128];  // zero-invariant
__device__ __align__(16) float g_agg2_u[(size_t)NUM_U * 128];  // zero-invariant
__device__ __align__(16) float g_agg2_i[(size_t)NUM_I * 128];  // zero-invariant
__device__ __align__(16) float g_p_u[(size_t)NUM_U * 128];     // h_u @ Wl2_ui
__device__ __align__(16) float g_p_i[(size_t)NUM_I * 128];     // h_i @ Wl2_iu
__device__ float g_dg_u[NUM_U];
__device__ float g_dg_i[NUM_I];
// fp16 activations (single-rounded)
__device__ __align__(16) uint16_t g_xf_u[(size_t)NUM_U * 128];
__device__ __align__(16) uint16_t g_xf_i[(size_t)NUM_I * 128];
__device__ __align__(16) uint16_t g_a1f_u[(size_t)NUM_U * 128];
__device__ __align__(16) uint16_t g_a1f_i[(size_t)NUM_I * 128];
__device__ __align__(16) uint16_t g_hf_u[(size_t)NUM_U * 256];
__device__ __align__(16) uint16_t g_hf_i[(size_t)NUM_I * 256];
// transposed fp16 hi/lo weights: 8 matrices x 32768 elems, [N][K] layout
__device__ __align__(16) uint16_t g_wT_h[8 * 32768];
__device__ __align__(16) uint16_t g_wT_l[8 * 32768];

// ---------------- zero ------------------------------------------------------
__global__ void zero_kernel(float4* __restrict__ p, int n4) {
    int i = blockIdx.x * blockDim.x + threadIdx.x;
    if (i < n4) p[i] = make_float4(0.f, 0.f, 0.f, 0.f);
}

// ---------------- degrees ---------------------------------------------------
__global__ void deg_kernel(const int* __restrict__ src, const int* __restrict__ dst,
                           float* __restrict__ dg_u, float* __restrict__ dg_i) {
    int e = blockIdx.x * blockDim.x + threadIdx.x;
    if (e < NUM_E) {
        atomicAdd(dg_u + src[e], 1.f);
        atomicAdd(dg_i + dst[e], 1.f);
    }
}
__global__ void invdeg_kernel(float* __restrict__ dg, int n) {
    int i = blockIdx.x * blockDim.x + threadIdx.x;
    if (i < n) dg[i] = 1.f / fmaxf(dg[i], 1.f);
}

// ---------------- scatter-add (segment sum), 128-wide rows ------------------
__global__ void scatter_kernel(const float* __restrict__ feat,
                               const int* __restrict__ gidx,
                               const int* __restrict__ sidx,
                               float* __restrict__ agg, int d4) {
    unsigned t = blockIdx.x * blockDim.x + threadIdx.x;
    unsigned e = t / d4;
    unsigned c = t % d4;
    if (e >= NUM_E) return;
    int g = gidx[e];
    int s = sidx[e];
    float4 v = reinterpret_cast<const float4*>(feat)[(size_t)g * d4 + c];
    float4* p = reinterpret_cast<float4*>(agg) + (size_t)s * d4 + c;
    asm volatile("red.global.add.v4.f32 [%0], {%1,%2,%3,%4};"
                 :: "l"(p), "f"(v.x), "f"(v.y), "f"(v.z), "f"(v.w) : "memory");
}

// ---------------- weight prep: transpose + fp16 hi/lo split -----------------
__global__ void prep_w(const float* __restrict__ W, uint16_t* __restrict__ oh,
                       uint16_t* __restrict__ ol, int K, int N) {
    int idx = blockIdx.x * blockDim.x + threadIdx.x;
    if (idx >= K * N) return;
    int k = idx / N, n = idx % N;
    float v = W[idx];
    __half h = __float2half_rn(v);
    float r = v - __half2float(h);
    __half l = __float2half_rn(r);
    oh[n * K + k] = *reinterpret_cast<uint16_t*>(&h);
    ol[n * K + k] = *reinterpret_cast<uint16_t*>(&l);
}

// ---------------- fp32 -> fp16 convert (opt: invdeg scale, zero src) --------
__global__ void cvt_kernel(const float4* in, float4* zro,
                           const float* __restrict__ inv,
                           uint2* __restrict__ of, int n4, int k4) {
    int i = blockIdx.x * blockDim.x + threadIdx.x;
    if (i >= n4) return;
    float4 v = in[i];
    if (inv) {
        float sc = inv[i / k4];
        v.x *= sc; v.y *= sc; v.z *= sc; v.w *= sc;
    }
    __half2 p01 = __float22half2_rn(make_float2(v.x, v.y));
    __half2 p23 = __float22half2_rn(make_float2(v.z, v.w));
    of[i] = make_uint2(*reinterpret_cast<uint32_t*>(&p01),
                       *reinterpret_cast<uint32_t*>(&p23));
    if (zro) zro[i] = make_float4(0.f, 0.f, 0.f, 0.f);
}

// ---------------- mma.sync helpers ------------------------------------------
__device__ __forceinline__ uint32_t smem_u32(const void* p) {
    uint32_t a;
    asm("{ .reg .u64 t; cvta.to.shared.u64 t, %1; cvt.u32.u64 %0, t; }"
        : "=r"(a) : "l"(p));
    return a;
}
__device__ __forceinline__ void ldm_x4(uint32_t addr, uint32_t& r0, uint32_t& r1,
                                       uint32_t& r2, uint32_t& r3) {
    asm volatile("ldmatrix.sync.aligned.m8n8.x4.shared.b16 {%0,%1,%2,%3}, [%4];"
                 : "=r"(r0), "=r"(r1), "=r"(r2), "=r"(r3) : "r"(addr));
}
__device__ __forceinline__ void mma_f16(float* c, const uint32_t* a,
                                        const uint32_t* b) {
    asm volatile(
        "mma.sync.aligned.m16n8k16.row.col.f32.f16.f16.f32 "
        "{%0,%1,%2,%3}, {%4,%5,%6,%7}, {%8,%9}, {%0,%1,%2,%3};"
        : "+f"(c[0]), "+f"(c[1]), "+f"(c[2]), "+f"(c[3])
        : "r"(a[0]), "r"(a[1]), "r"(a[2]), "r"(a[3]), "r"(b[0]), "r"(b[1]));
}
__device__ __forceinline__ void cp16(uint32_t dst, const void* src, int sz) {
    asm volatile("cp.async.cg.shared.global [%0], [%1], 16, %2;"
                 :: "r"(dst), "l"(src), "r"(sz) : "memory");
}

// ---------------- fused SAGE GEMM: fp16 A (single) x fp16 W (hi/lo) ---------
// Two-phase (A0 != null):  C = eps( A0@Wl + A1@Wr )   [Wl=Bl*, Wr=Br*]
// Single-phase (A0 == null): C = eps( A1@Wl )
// eps(v): if Eagg: v += inv[m]*Eagg[m,n]; if bias: v = relu(v + bias[n]).
// Optional: emit fp16 of result (Hf); zero Eagg tile (zeroE, gridDim.x==1).
// CTA tile 128x128, 8 warps of 64x32, BK=64, cp.async double buffer.
#define SROW 72                      // fp16 elems per smem row (64 + 8 pad)
#define TILE_B (128 * SROW * 2)      // 18432 bytes per operand tile
#define STAGE_B (3 * TILE_B)         // A, Bh, Bl
#define GEMM_SMEM (2 * STAGE_B)      // 110592
__global__ void __launch_bounds__(256)
sage_gemm_f16(const uint16_t* __restrict__ A0, const uint16_t* __restrict__ A1,
              const uint16_t* __restrict__ Blh, const uint16_t* __restrict__ Bll,
              const uint16_t* __restrict__ Brh, const uint16_t* __restrict__ Brl,
              const float* __restrict__ bias, float* __restrict__ C,
              uint16_t* __restrict__ Hf,
              const float* __restrict__ Eagg, const float* __restrict__ inv,
              float* __restrict__ zeroE,
              int M, int K, int N) {
    extern __shared__ __align__(16) uint16_t smem[];
    const uint32_t sbase = smem_u32(smem);

    const int tid = threadIdx.x;
    const int wid = tid >> 5, lane = tid & 31;
    const int wm = wid >> 2, wn = wid & 3;
    const int rowBase = blockIdx.y * 128, colBase = blockIdx.x * 128;
    const int cpp = K >> 6;
    const bool twoPhase = (A0 != nullptr);
    const int nch = (twoPhase ? 2 : 1) * cpp;
    const uint16_t* a0 = twoPhase ? A0 : A1;

    const int ldR0 = tid >> 3, ldS = tid & 7;

    const int aRow = lane & 15, aColH = (lane >> 4) * 8;
    const int bRow = ((lane >> 4) & 1) * 8 + (lane & 7);
    const int bColH = ((lane >> 3) & 1) * 8;

    float acc[4][4][4];
#pragma unroll
    for (int i = 0; i < 4; ++i)
#pragma unroll
        for (int j = 0; j < 4; ++j)
#pragma unroll
            for (int k = 0; k < 4; ++k) acc[i][j][k] = 0.f;

    auto issue = [&](int c) {
        const int phase = (c >= cpp) ? 1 : 0;
        const int k0 = (c - (phase ? cpp : 0)) * 64;
        const uint16_t* a = phase ? A1 : a0;
        const uint16_t* bh = phase ? Brh : Blh;
        const uint16_t* bl = phase ? Brl : Bll;
        const uint32_t st = sbase + (c & 1) * STAGE_B;
#pragma unroll
        for (int it = 0; it < 4; ++it) {
            const int r = ldR0 + it * 32;
            const uint32_t doff = r * (SROW * 2) + ldS * 16;
            const int grow = rowBase + r;
            const int sz = (grow < M) ? 16 : 0;
            const size_t aoff = (size_t)(grow < M ? grow : 0) * K + k0 + ldS * 8;
            cp16(st + doff, a + aoff, sz);
            const size_t boff = (size_t)(colBase + r) * K + k0 + ldS * 8;
            cp16(st + TILE_B + doff, bh + boff, 16);
            cp16(st + 2 * TILE_B + doff, bl + boff, 16);
        }
        asm volatile("cp.async.commit_group;" ::: "memory");
    };

    issue(0);
    if (nch > 1) issue(1);

    for (int c = 0; c < nch; ++c) {
        if (c + 1 < nch)
            asm volatile("cp.async.wait_group 1;" ::: "memory");
        else
            asm volatile("cp.async.wait_group 0;" ::: "memory");
        __syncthreads();

        const uint32_t st = sbase + (c & 1) * STAGE_B;
#pragma unroll
        for (int ks = 0; ks < 4; ++ks) {
            const int kk = ks * 16;
            uint32_t af[4][4];
#pragma unroll
            for (int fm = 0; fm < 4; ++fm) {
                uint32_t off = st + 2u * ((wm * 64 + fm * 16 + aRow) * SROW + kk + aColH);
                ldm_x4(off, af[fm][0], af[fm][1], af[fm][2], af[fm][3]);
            }
            uint32_t bh[4][2], bl[4][2];
#pragma unroll
            for (int g = 0; g < 2; ++g) {
                uint32_t off = st + TILE_B +
                               2u * ((wn * 32 + g * 16 + bRow) * SROW + kk + bColH);
                ldm_x4(off, bh[2 * g][0], bh[2 * g][1], bh[2 * g + 1][0], bh[2 * g + 1][1]);
                ldm_x4(off + TILE_B, bl[2 * g][0], bl[2 * g][1],
                       bl[2 * g + 1][0], bl[2 * g + 1][1]);
            }
#pragma unroll
            for (int fm = 0; fm < 4; ++fm)
#pragma unroll
                for (int fn = 0; fn < 4; ++fn) {
                    mma_f16(acc[fm][fn], af[fm], bh[fn]);
                    mma_f16(acc[fm][fn], af[fm], bl[fn]);
                }
        }
        __syncthreads();
        if (c + 2 < nch) issue(c + 2);
    }

    // ---- epilogue ----
#pragma unroll
    for (int fm = 0; fm < 4; ++fm) {
        const int r0 = rowBase + wm * 64 + fm * 16 + (lane >> 2);
        const int r1 = r0 + 8;
#pragma unroll
        for (int fn = 0; fn < 4; ++fn) {
            const int col = colBase + wn * 32 + fn * 8 + (lane & 3) * 2;
#pragma unroll
            for (int half = 0; half < 2; ++half) {
                const int rr = half ? r1 : r0;
                if (rr >= M) continue;
                float vx = acc[fm][fn][half * 2 + 0];
                float vy = acc[fm][fn][half * 2 + 1];
                const size_t off = (size_t)rr * N + col;
                if (Eagg) {
                    float2 e = *(const float2*)(Eagg + off);
                    float s = inv[rr];
                    vx += s * e.x;
                    vy += s * e.y;
                }
                if (bias) {
                    vx = fmaxf(vx + bias[col], 0.f);
                    vy = fmaxf(vy + bias[col + 1], 0.f);
                }
                if (C) *(float2*)(C + off) = make_float2(vx, vy);
                if (Hf) {
                    __half2 hp = __float22half2_rn(make_float2(vx, vy));
                    *(uint32_t*)(Hf + off) = *reinterpret_cast<uint32_t*>(&hp);
                }
            }
        }
    }

    // ---- fused re-zero of Eagg tile (sole reader when gridDim.x == 1) ----
    if (zeroE) {
        __syncthreads();
        const int n4 = N >> 2;
        for (int i = tid; i < 128 * n4; i += 256) {
            const int r = i / n4, cc = i % n4;
            if (rowBase + r < M)
                reinterpret_cast<float4*>(zeroE + (size_t)(rowBase + r) * N)[cc] =
                    make_float4(0.f, 0.f, 0.f, 0.f);
        }
    }
}

// ---------------- host launch ------------------------------------------------
static inline int cdiv(int a, int b) { return (a + b - 1) / b; }

extern "C" void kernel_launch(void* const* d_in, const int* in_sizes, int n_in,
                              void* d_out, int out_size) {
    const float* x_user = (const float*)d_in[0];
    const float* x_item = (const float*)d_in[1];
    const int* e_src = (const int*)d_in[2];
    const int* e_dst = (const int*)d_in[3];
    const float* Wl1_ui = (const float*)d_in[4];
    const float* Wr1_ui = (const float*)d_in[5];
    const float* bl1_ui = (const float*)d_in[6];
    const float* Wl1_iu = (const float*)d_in[7];
    const float* Wr1_iu = (const float*)d_in[8];
    const float* bl1_iu = (const float*)d_in[9];
    const float* Wl2_ui = (const float*)d_in[10];
    const float* Wr2_ui = (const float*)d_in[11];
    const float* bl2_ui = (const float*)d_in[12];
    const float* Wl2_iu = (const float*)d_in[13];
    const float* Wr2_iu = (const float*)d_in[14];
    const float* bl2_iu = (const float*)d_in[15];
    float* out = (float*)d_out;

    float *a1_u, *a1_i, *a2_u, *a2_i, *p_u, *p_i, *dg_u, *dg_i;
    uint16_t *xf_u, *xf_i, *a1f_u, *a1f_i, *hf_u, *hf_i, *wTh, *wTl;
    cudaGetSymbolAddress((void**)&a1_u, g_agg1_u);
    cudaGetSymbolAddress((void**)&a1_i, g_agg1_i);
    cudaGetSymbolAddress((void**)&a2_u, g_agg2_u);
    cudaGetSymbolAddress((void**)&a2_i, g_agg2_i);
    cudaGetSymbolAddress((void**)&p_u, g_p_u);
    cudaGetSymbolAddress((void**)&p_i, g_p_i);
    cudaGetSymbolAddress((void**)&dg_u, g_dg_u);
    cudaGetSymbolAddress((void**)&dg_i, g_dg_i);
    cudaGetSymbolAddress((void**)&xf_u, g_xf_u);
    cudaGetSymbolAddress((void**)&xf_i, g_xf_i);
    cudaGetSymbolAddress((void**)&a1f_u, g_a1f_u);
    cudaGetSymbolAddress((void**)&a1f_i, g_a1f_i);
    cudaGetSymbolAddress((void**)&hf_u, g_hf_u);
    cudaGetSymbolAddress((void**)&hf_i, g_hf_i);
    cudaGetSymbolAddress((void**)&wTh, g_wT_h);
    cudaGetSymbolAddress((void**)&wTl, g_wT_l);

    cudaFuncSetAttribute(sage_gemm_f16, cudaFuncAttributeMaxDynamicSharedMemorySize,
                         GEMM_SMEM);

    const int TB = 256;

    // --- x converts, dg zero, deg ---
    cvt_kernel<<<cdiv(NUM_U * 32, TB), TB>>>((const float4*)x_user, nullptr, nullptr,
                                             (uint2*)xf_u, NUM_U * 32, 32);
    cvt_kernel<<<cdiv(NUM_I * 32, TB), TB>>>((const float4*)x_item, nullptr, nullptr,
                                             (uint2*)xf_i, NUM_I * 32, 32);
    zero_kernel<<<cdiv(NUM_U / 4, TB), TB>>>((float4*)dg_u, NUM_U / 4);
    zero_kernel<<<cdiv(NUM_I / 4, TB), TB>>>((float4*)dg_i, NUM_I / 4);
    deg_kernel<<<cdiv(NUM_E, TB), TB>>>(e_src, e_dst, dg_u, dg_i);

    // --- layer-1 scatter (agg1 zero by invariant; D=128 -> d4=32) ---
    {
        int nb = cdiv(NUM_E * 32, TB);
        scatter_kernel<<<nb, TB>>>(x_user, e_src, e_dst, a1_i, 32);
        scatter_kernel<<<nb, TB>>>(x_item, e_dst, e_src, a1_u, 32);
    }

    invdeg_kernel<<<cdiv(NUM_U, TB), TB>>>(dg_u, NUM_U);
    invdeg_kernel<<<cdiv(NUM_I, TB), TB>>>(dg_i, NUM_I);

    // --- weight prep: transpose + fp16 hi/lo split ---
    {
        const float* Ws[8] = {Wl1_ui, Wr1_ui, Wl1_iu, Wr1_iu,
                              Wl2_ui, Wr2_ui, Wl2_iu, Wr2_iu};
        const int Ks[8] = {128, 128, 128, 128, 256, 256, 256, 256};
        const int Ns[8] = {256, 256, 256, 256, 128, 128, 128, 128};
        for (int m = 0; m < 8; ++m)
            prep_w<<<cdiv(32768, TB), TB>>>(Ws[m], wTh + m * 32768, wTl + m * 32768,
                                            Ks[m], Ns[m]);
    }

    // --- layer-1 agg convert (scale by invdeg, re-zero agg1) ---
    cvt_kernel<<<cdiv(NUM_I * 32, TB), TB>>>((const float4*)a1_i, (float4*)a1_i,
                                             dg_i, (uint2*)a1f_i, NUM_I * 32, 32);
    cvt_kernel<<<cdiv(NUM_U * 32, TB), TB>>>((const float4*)a1_u, (float4*)a1_u,
                                             dg_u, (uint2*)a1f_u, NUM_U * 32, 32);

    // --- layer-1 GEMMs: two-phase [M,128]@[128,256]; emit h fp16 only ---
    {
        dim3 gi(2, cdiv(NUM_I, 128));
        sage_gemm_f16<<<gi, 256, GEMM_SMEM>>>(a1f_i, xf_i,
            wTh + 0 * 32768, wTl + 0 * 32768, wTh + 1 * 32768, wTl + 1 * 32768,
            bl1_ui, nullptr, hf_i, nullptr, nullptr, nullptr,
            NUM_I, DIM_D, DIM_H);
        dim3 gu(2, cdiv(NUM_U, 128));
        sage_gemm_f16<<<gu, 256, GEMM_SMEM>>>(a1f_u, xf_u,
            wTh + 2 * 32768, wTl + 2 * 32768, wTh + 3 * 32768, wTl + 3 * 32768,
            bl1_iu, nullptr, hf_u, nullptr, nullptr, nullptr,
            NUM_U, DIM_D, DIM_H);
    }

    // --- projection GEMMs (project-first): p = h @ Wl2, linear, fp32 out ---
    {
        dim3 gu(1, cdiv(NUM_U, 128));
        sage_gemm_f16<<<gu, 256, GEMM_SMEM>>>(nullptr, hf_u,
            wTh + 4 * 32768, wTl + 4 * 32768, nullptr, nullptr,
            nullptr, p_u, nullptr, nullptr, nullptr, nullptr,
            NUM_U, DIM_H, DIM_O);
        dim3 gi(1, cdiv(NUM_I, 128));
        sage_gemm_f16<<<gi, 256, GEMM_SMEM>>>(nullptr, hf_i,
            wTh + 6 * 32768, wTl + 6 * 32768, nullptr, nullptr,
            nullptr, p_i, nullptr, nullptr, nullptr, nullptr,
            NUM_I, DIM_H, DIM_O);
    }

    // --- layer-2 scatter: scatter projected p (128-wide) ---
    {
        int nb = cdiv(NUM_E * 32, TB);
        scatter_kernel<<<nb, TB>>>(p_u, e_src, e_dst, a2_i, 32);
        scatter_kernel<<<nb, TB>>>(p_i, e_dst, e_src, a2_u, 32);
    }

    // --- layer-2 GEMMs: single-phase h@Wr2 + epilogue inv*agg2 + bias + relu;
    //     epilogue re-zeroes agg2 (gridDim.x == 1) ---
    {
        dim3 gi(1, cdiv(NUM_I, 128));
        sage_gemm_f16<<<gi, 256, GEMM_SMEM>>>(nullptr, hf_i,
            wTh + 5 * 32768, wTl + 5 * 32768, nullptr, nullptr,
            bl2_ui, out + (size_t)NUM_U * DIM_O, nullptr,
            a2_i, dg_i, a2_i, NUM_I, DIM_H, DIM_O);
        dim3 gu(1, cdiv(NUM_U, 128));
        sage_gemm_f16<<<gu, 256, GEMM_SMEM>>>(nullptr, hf_u,
            wTh + 7 * 32768, wTl + 7 * 32768, nullptr, nullptr,
            bl2_iu, out, nullptr,
            a2_u, dg_u, a2_u, NUM_U, DIM_H, DIM_O);
    }
}